// round 4
// baseline (speedup 1.0000x reference)
#include <cuda_runtime.h>
#include <cstdint>

#define NN 50000
#define RR 16
#define DD 200
#define EE 400000

#define BM 64
#define TK 8
#define NT 160   // 16 rowgrps x 10 colgrps, 4x20 thread tile

#define NSEG (RR * NN)              // 800000
#define NBLK ((NSEG + 1023) / 1024) // 782

// ---------------- scratch (device globals; no runtime allocation) ----------
__device__ float g_mean[(size_t)RR * NN * DD]; // compact mean rows per (r, pos)
__device__ int   g_cnt[NSEG];                  // per-(r,dst) edge counts
__device__ int   g_cur[NSEG];                  // fill cursors
__device__ int   g_off[NSEG];                  // CSR offsets (exclusive scan)
__device__ int   g_bsum[1024];                 // scan block sums
__device__ int   g_srcids[EE];                 // CSR: src node per edge slot
__device__ int   g_list[NSEG];                 // per-relation active dst list
__device__ int   g_listcnt[RR];                // active count per relation
__device__ float g_h[NN * DD];                 // layer-1 activations

__device__ __forceinline__ void red4(float* p, float4 v) {
    asm volatile("red.global.add.v4.f32 [%0], {%1,%2,%3,%4};"
                 :: "l"(p), "f"(v.x), "f"(v.y), "f"(v.z), "f"(v.w)
                 : "memory");
}

// ---------------- one-time graph preprocessing ------------------------------

__global__ void k_init() {
    int stride = gridDim.x * blockDim.x;
    for (int i = blockIdx.x * blockDim.x + threadIdx.x; i < NSEG; i += stride) {
        g_cnt[i] = 0;
        g_cur[i] = 0;
    }
    if (blockIdx.x == 0 && threadIdx.x < RR) g_listcnt[threadIdx.x] = 0;
}

__global__ void k_count(const int* __restrict__ dst, const int* __restrict__ et) {
    int e = blockIdx.x * blockDim.x + threadIdx.x;
    if (e >= EE) return;
    atomicAdd(&g_cnt[et[e] * NN + dst[e]], 1);
}

__global__ void k_scan1() {
    __shared__ int sh[1024];
    int i = blockIdx.x * 1024 + threadIdx.x;
    int v = (i < NSEG) ? g_cnt[i] : 0;
    sh[threadIdx.x] = v;
    __syncthreads();
    #pragma unroll
    for (int d = 1; d < 1024; d <<= 1) {
        int t = (threadIdx.x >= d) ? sh[threadIdx.x - d] : 0;
        __syncthreads();
        sh[threadIdx.x] += t;
        __syncthreads();
    }
    if (i < NSEG) g_off[i] = sh[threadIdx.x] - v;     // exclusive within block
    if (threadIdx.x == 1023) g_bsum[blockIdx.x] = sh[1023];
}

__global__ void k_scan2() {   // single block of 1024
    __shared__ int sh[1024];
    int v = (threadIdx.x < NBLK) ? g_bsum[threadIdx.x] : 0;
    sh[threadIdx.x] = v;
    __syncthreads();
    #pragma unroll
    for (int d = 1; d < 1024; d <<= 1) {
        int t = (threadIdx.x >= d) ? sh[threadIdx.x - d] : 0;
        __syncthreads();
        sh[threadIdx.x] += t;
        __syncthreads();
    }
    g_bsum[threadIdx.x] = sh[threadIdx.x] - v;        // exclusive
}

__global__ void k_scan3() {
    int i = blockIdx.x * 1024 + threadIdx.x;
    if (i < NSEG) g_off[i] += g_bsum[blockIdx.x];
}

__global__ void k_fill(const int* __restrict__ src, const int* __restrict__ dst,
                       const int* __restrict__ et) {
    int e = blockIdx.x * blockDim.x + threadIdx.x;
    if (e >= EE) return;
    int seg = et[e] * NN + dst[e];
    int pos = g_off[seg] + atomicAdd(&g_cur[seg], 1);
    g_srcids[pos] = src[e];
}

__global__ void k_compact() {
    int i = blockIdx.x * blockDim.x + threadIdx.x;
    if (i >= NSEG) return;
    if (g_cnt[i] > 0) {
        int r = i / NN, n = i - r * NN;
        int p = atomicAdd(&g_listcnt[r], 1);
        g_list[r * NN + p] = n;
    }
}

// ---------------- per-layer kernels -----------------------------------------

// one warp per active (r, pos): gather src rows of x, average, write g_mean
__global__ void k_mean(const float* __restrict__ x) {
    int wid = threadIdx.x >> 5, lane = threadIdx.x & 31;
    int p = blockIdx.x * (blockDim.x >> 5) + wid;
    int r = blockIdx.y;
    if (p >= g_listcnt[r]) return;
    int n = g_list[r * NN + p];
    int seg = r * NN + n;
    int o0 = g_off[seg];
    int deg = g_cnt[seg];
    float inv = 1.0f / (float)deg;

    float4 a0 = make_float4(0.f, 0.f, 0.f, 0.f);
    float4 a1 = a0;
    for (int e = 0; e < deg; e++) {
        const float4* xr = (const float4*)(x + (size_t)g_srcids[o0 + e] * DD);
        float4 v = xr[lane];
        a0.x += v.x; a0.y += v.y; a0.z += v.z; a0.w += v.w;
        if (lane < 18) {
            float4 w = xr[lane + 32];
            a1.x += w.x; a1.y += w.y; a1.z += w.z; a1.w += w.w;
        }
    }
    float4* mp = (float4*)(g_mean + ((size_t)r * NN + p) * DD);
    a0.x *= inv; a0.y *= inv; a0.z *= inv; a0.w *= inv;
    mp[lane] = a0;
    if (lane < 18) {
        a1.x *= inv; a1.y *= inv; a1.z *= inv; a1.w *= inv;
        mp[lane + 32] = a1;
    }
}

__global__ void k_relu() {
    float4* h4 = (float4*)g_h;
    const int n4 = NN * DD / 4;
    for (int i = blockIdx.x * blockDim.x + threadIdx.x; i < n4;
         i += gridDim.x * blockDim.x) {
        float4 v = h4[i];
        v.x = fmaxf(v.x, 0.f); v.y = fmaxf(v.y, 0.f);
        v.z = fmaxf(v.z, 0.f); v.w = fmaxf(v.w, 0.f);
        h4[i] = v;
    }
}

// GEMM. REL=false: out[n,:] = A[n,:] @ W + bias   (dense rows, plain store)
//       REL=true : out[g_list[r,p],:] += g_mean[r,p,:] @ W[r]  (red4 accumulate)
template <bool REL>
__global__ __launch_bounds__(NT, 3)
void k_gemm(const float* __restrict__ A,
            const float* __restrict__ W,
            const float* __restrict__ bias,
            float* __restrict__ out) {
    __shared__ float As[TK][BM];
    __shared__ float Bs[TK][DD];

    const int r  = REL ? blockIdx.y : 0;
    const int m0 = blockIdx.x * BM;

    int valid = REL ? (g_listcnt[r] - m0) : (NN - m0);
    if (valid <= 0) return;
    if (valid > BM) valid = BM;

    const int tid = threadIdx.x;
    const float* Ab = REL ? (g_mean + (size_t)r * NN * DD) : A;
    const float* Wr = REL ? (W + (size_t)r * DD * DD) : W;

    const int arow  = tid >> 1;      // A-load row (tid<128)
    const int apart = tid & 1;

    // ---- prefetch tile k0=0 into registers ----
    float4 pa = make_float4(0.f, 0.f, 0.f, 0.f);
    float4 pb0, pb1, pb2;
    if (tid < 128 && arow < valid)
        pa = *(const float4*)(Ab + (size_t)(m0 + arow) * DD + apart * 4);
    {
        const float4* w4 = (const float4*)Wr;  // k0 = 0
        pb0 = w4[tid];
        pb1 = w4[tid + 160];
        if (tid < 80) pb2 = w4[tid + 320];
    }

    float acc[4][20];
    #pragma unroll
    for (int i = 0; i < 4; i++)
        #pragma unroll
        for (int j = 0; j < 20; j++) acc[i][j] = 0.f;

    const int rowgrp = tid / 10;
    const int colgrp = tid - rowgrp * 10;
    const int c0 = colgrp * 20;

    for (int k0 = 0; k0 < DD; k0 += TK) {
        // store prefetched tile to smem
        if (tid < 128) {
            int kb = apart * 4;
            As[kb + 0][arow] = pa.x; As[kb + 1][arow] = pa.y;
            As[kb + 2][arow] = pa.z; As[kb + 3][arow] = pa.w;
        }
        {
            float4* b4 = (float4*)&Bs[0][0];
            b4[tid] = pb0;
            b4[tid + 160] = pb1;
            if (tid < 80) b4[tid + 320] = pb2;
        }
        __syncthreads();

        // prefetch next tile
        int kn = k0 + TK;
        if (kn < DD) {
            pa = make_float4(0.f, 0.f, 0.f, 0.f);
            if (tid < 128 && arow < valid)
                pa = *(const float4*)(Ab + (size_t)(m0 + arow) * DD + kn + apart * 4);
            const float4* w4 = (const float4*)(Wr + (size_t)kn * DD);
            pb0 = w4[tid];
            pb1 = w4[tid + 160];
            if (tid < 80) pb2 = w4[tid + 320];
        }

        // compute
        #pragma unroll
        for (int kk = 0; kk < TK; kk++) {
            float4 a = *(const float4*)&As[kk][rowgrp * 4];
            #pragma unroll
            for (int jj = 0; jj < 5; jj++) {
                int j = jj + colgrp;
                j = (j >= 5) ? (j - 5) : j;           // stagger: kill bank conflicts
                j = (j >= 5) ? (j - 5) : j;
                float4 b = *(const float4*)&Bs[kk][c0 + j * 4];
                acc[0][j*4+0] = fmaf(a.x, b.x, acc[0][j*4+0]);
                acc[0][j*4+1] = fmaf(a.x, b.y, acc[0][j*4+1]);
                acc[0][j*4+2] = fmaf(a.x, b.z, acc[0][j*4+2]);
                acc[0][j*4+3] = fmaf(a.x, b.w, acc[0][j*4+3]);
                acc[1][j*4+0] = fmaf(a.y, b.x, acc[1][j*4+0]);
                acc[1][j*4+1] = fmaf(a.y, b.y, acc[1][j*4+1]);
                acc[1][j*4+2] = fmaf(a.y, b.z, acc[1][j*4+2]);
                acc[1][j*4+3] = fmaf(a.y, b.w, acc[1][j*4+3]);
                acc[2][j*4+0] = fmaf(a.z, b.x, acc[2][j*4+0]);
                acc[2][j*4+1] = fmaf(a.z, b.y, acc[2][j*4+1]);
                acc[2][j*4+2] = fmaf(a.z, b.z, acc[2][j*4+2]);
                acc[2][j*4+3] = fmaf(a.z, b.w, acc[2][j*4+3]);
                acc[3][j*4+0] = fmaf(a.w, b.x, acc[3][j*4+0]);
                acc[3][j*4+1] = fmaf(a.w, b.y, acc[3][j*4+1]);
                acc[3][j*4+2] = fmaf(a.w, b.z, acc[3][j*4+2]);
                acc[3][j*4+3] = fmaf(a.w, b.w, acc[3][j*4+3]);
            }
        }
        __syncthreads();
    }

    // epilogue
    #pragma unroll
    for (int i = 0; i < 4; i++) {
        int row = rowgrp * 4 + i;
        if (row >= valid) continue;
        int n = REL ? g_list[r * NN + m0 + row] : (m0 + row);
        float* op = out + (size_t)n * DD + c0;
        if (REL) {
            #pragma unroll
            for (int j = 0; j < 5; j++) {
                float4 v = make_float4(acc[i][j*4+0], acc[i][j*4+1],
                                       acc[i][j*4+2], acc[i][j*4+3]);
                red4(op + j * 4, v);
            }
        } else {
            #pragma unroll
            for (int j = 0; j < 5; j++) {
                float4 v;
                v.x = acc[i][j*4+0] + bias[c0 + j*4 + 0];
                v.y = acc[i][j*4+1] + bias[c0 + j*4 + 1];
                v.z = acc[i][j*4+2] + bias[c0 + j*4 + 2];
                v.w = acc[i][j*4+3] + bias[c0 + j*4 + 3];
                *(float4*)(op + j * 4) = v;
            }
        }
    }
}

// ---------------- launch -----------------------------------------------------

extern "C" void kernel_launch(void* const* d_in, const int* in_sizes, int n_in,
                              void* d_out, int out_size) {
    const int*   ei    = (const int*)d_in[0];
    const int*   et    = (const int*)d_in[1];
    const float* emb   = (const float*)d_in[2];
    const float* W1    = (const float*)d_in[3];
    const float* root1 = (const float*)d_in[4];
    const float* b1    = (const float*)d_in[5];
    const float* W2    = (const float*)d_in[6];
    const float* root2 = (const float*)d_in[7];
    const float* b2    = (const float*)d_in[8];
    float* out = (float*)d_out;

    const int* src = ei;
    const int* dst = ei + EE;

    float* hptr = nullptr;
    cudaGetSymbolAddress((void**)&hptr, g_h);

    const int mb = (NN + BM - 1) / BM;          // 782
    const int eb = (EE + 255) / 256;
    const int sb = (NSEG + 255) / 256;

    // ---- one-time CSR + compaction (graph is layer-invariant) ----
    k_init<<<1024, 256>>>();
    k_count<<<eb, 256>>>(dst, et);
    k_scan1<<<NBLK, 1024>>>();
    k_scan2<<<1, 1024>>>();
    k_scan3<<<NBLK, 1024>>>();
    k_fill<<<eb, 256>>>(src, dst, et);
    k_compact<<<sb, 256>>>();

    // ---- layer 1 ----
    k_mean<<<dim3((NN + 7) / 8, RR), 256>>>(emb);
    k_gemm<false><<<dim3(mb, 1), NT>>>(emb, root1, b1, hptr);
    k_gemm<true ><<<dim3(mb, RR), NT>>>(nullptr, W1, nullptr, hptr);
    k_relu<<<2048, 256>>>();

    // ---- layer 2 ----
    k_mean<<<dim3((NN + 7) / 8, RR), 256>>>(hptr);
    k_gemm<false><<<dim3(mb, 1), NT>>>(hptr, root2, b2, out);
    k_gemm<true ><<<dim3(mb, RR), NT>>>(nullptr, W2, nullptr, out);
}

// round 5
// speedup vs baseline: 29.5097x; 29.5097x over previous
#include <cuda_runtime.h>
#include <cstdint>

#define NN 50000
#define RR 16
#define DD 200
#define EE 400000

#define BM 64
#define TK 8
#define NT 160   // 16 rowgrps x 10 colgrps, 4x20 register tile (compile-time idx!)

#define NSEG (RR * NN)              // 800000
#define NBLK ((NSEG + 1023) / 1024) // 782

// ---------------- scratch (device globals; no runtime allocation) ----------
__device__ float g_mean[(size_t)RR * NN * DD]; // compact mean rows per (r,pos)
__device__ int   g_cnt[NSEG];
__device__ int   g_cur[NSEG];
__device__ int   g_off[NSEG];
__device__ int   g_bsum[1024];
__device__ int   g_srcids[EE];
__device__ int   g_list[NSEG];
__device__ int   g_listcnt[RR];
__device__ float g_h[NN * DD];

__device__ __forceinline__ void red4(float* p, float4 v) {
    asm volatile("red.global.add.v4.f32 [%0], {%1,%2,%3,%4};"
                 :: "l"(p), "f"(v.x), "f"(v.y), "f"(v.z), "f"(v.w)
                 : "memory");
}

// ---------------- one-time graph preprocessing ------------------------------

__global__ void k_init() {
    int stride = gridDim.x * blockDim.x;
    for (int i = blockIdx.x * blockDim.x + threadIdx.x; i < NSEG; i += stride) {
        g_cnt[i] = 0;
        g_cur[i] = 0;
    }
    if (blockIdx.x == 0 && threadIdx.x < RR) g_listcnt[threadIdx.x] = 0;
}

__global__ void k_count(const int* __restrict__ dst, const int* __restrict__ et) {
    int e = blockIdx.x * blockDim.x + threadIdx.x;
    if (e >= EE) return;
    atomicAdd(&g_cnt[et[e] * NN + dst[e]], 1);
}

__global__ void k_scan1() {
    __shared__ int sh[1024];
    int i = blockIdx.x * 1024 + threadIdx.x;
    int v = (i < NSEG) ? g_cnt[i] : 0;
    sh[threadIdx.x] = v;
    __syncthreads();
    #pragma unroll
    for (int d = 1; d < 1024; d <<= 1) {
        int t = (threadIdx.x >= d) ? sh[threadIdx.x - d] : 0;
        __syncthreads();
        sh[threadIdx.x] += t;
        __syncthreads();
    }
    if (i < NSEG) g_off[i] = sh[threadIdx.x] - v;
    if (threadIdx.x == 1023) g_bsum[blockIdx.x] = sh[1023];
}

__global__ void k_scan2() {
    __shared__ int sh[1024];
    int v = (threadIdx.x < NBLK) ? g_bsum[threadIdx.x] : 0;
    sh[threadIdx.x] = v;
    __syncthreads();
    #pragma unroll
    for (int d = 1; d < 1024; d <<= 1) {
        int t = (threadIdx.x >= d) ? sh[threadIdx.x - d] : 0;
        __syncthreads();
        sh[threadIdx.x] += t;
        __syncthreads();
    }
    g_bsum[threadIdx.x] = sh[threadIdx.x] - v;
}

__global__ void k_scan3() {
    int i = blockIdx.x * 1024 + threadIdx.x;
    if (i < NSEG) g_off[i] += g_bsum[blockIdx.x];
}

__global__ void k_fill(const int* __restrict__ src, const int* __restrict__ dst,
                       const int* __restrict__ et) {
    int e = blockIdx.x * blockDim.x + threadIdx.x;
    if (e >= EE) return;
    int seg = et[e] * NN + dst[e];
    int pos = g_off[seg] + atomicAdd(&g_cur[seg], 1);
    g_srcids[pos] = src[e];
}

__global__ void k_compact() {
    int i = blockIdx.x * blockDim.x + threadIdx.x;
    if (i >= NSEG) return;
    if (g_cnt[i] > 0) {
        int r = i / NN, n = i - r * NN;
        int p = atomicAdd(&g_listcnt[r], 1);
        g_list[r * NN + p] = n;
    }
}

// ---------------- per-layer kernels -----------------------------------------

// one warp per active (r,pos): gather src rows of x, average, write g_mean
__global__ void k_mean(const float* __restrict__ x) {
    int wid = threadIdx.x >> 5, lane = threadIdx.x & 31;
    int p = blockIdx.x * (blockDim.x >> 5) + wid;
    int r = blockIdx.y;
    if (p >= g_listcnt[r]) return;
    int n = g_list[r * NN + p];
    int seg = r * NN + n;
    int o0 = g_off[seg];
    int deg = g_cnt[seg];
    float inv = 1.0f / (float)deg;

    float4 a0 = make_float4(0.f, 0.f, 0.f, 0.f);
    float4 a1 = a0;
    for (int e = 0; e < deg; e++) {
        const float4* xr = (const float4*)(x + (size_t)g_srcids[o0 + e] * DD);
        float4 v = xr[lane];
        a0.x += v.x; a0.y += v.y; a0.z += v.z; a0.w += v.w;
        if (lane < 18) {
            float4 w = xr[lane + 32];
            a1.x += w.x; a1.y += w.y; a1.z += w.z; a1.w += w.w;
        }
    }
    float4* mp = (float4*)(g_mean + ((size_t)r * NN + p) * DD);
    a0.x *= inv; a0.y *= inv; a0.z *= inv; a0.w *= inv;
    mp[lane] = a0;
    if (lane < 18) {
        a1.x *= inv; a1.y *= inv; a1.z *= inv; a1.w *= inv;
        mp[lane + 32] = a1;
    }
}

__global__ void k_relu() {
    float4* h4 = (float4*)g_h;
    const int n4 = NN * DD / 4;
    for (int i = blockIdx.x * blockDim.x + threadIdx.x; i < n4;
         i += gridDim.x * blockDim.x) {
        float4 v = h4[i];
        v.x = fmaxf(v.x, 0.f); v.y = fmaxf(v.y, 0.f);
        v.z = fmaxf(v.z, 0.f); v.w = fmaxf(v.w, 0.f);
        h4[i] = v;
    }
}

// GEMM. REL=false: out[n,:] = A[n,:] @ W + bias   (dense rows, plain store)
//       REL=true : out[g_list[r,p],:] += g_mean[r,p,:] @ W[r] (red4 accumulate)
// NOTE: every acc[][] index below is compile-time constant (no spills).
template <bool REL>
__global__ __launch_bounds__(NT, 2)
void k_gemm(const float* __restrict__ A,
            const float* __restrict__ W,
            const float* __restrict__ bias,
            float* __restrict__ out) {
    __shared__ float As[TK][BM];
    __shared__ float Bs[TK][DD];

    const int r  = REL ? blockIdx.y : 0;
    const int m0 = blockIdx.x * BM;

    int valid = REL ? (g_listcnt[r] - m0) : (NN - m0);
    if (valid <= 0) return;
    if (valid > BM) valid = BM;

    const int tid = threadIdx.x;
    const float* Ab = REL ? (g_mean + (size_t)r * NN * DD) : A;
    const float* Wr = REL ? (W + (size_t)r * DD * DD) : W;

    const int arow  = tid >> 1;   // rows 0..63 for tid<128
    const int apart = tid & 1;

    // ---- prefetch tile k0=0 into registers ----
    float4 pa = make_float4(0.f, 0.f, 0.f, 0.f);
    float4 pb0, pb1, pb2;
    if (tid < 128 && arow < valid)
        pa = *(const float4*)(Ab + (size_t)(m0 + arow) * DD + apart * 4);
    {
        const float4* w4 = (const float4*)Wr;
        pb0 = w4[tid];
        pb1 = w4[tid + 160];
        if (tid < 80) pb2 = w4[tid + 320];
    }

    float acc[4][20];
    #pragma unroll
    for (int i = 0; i < 4; i++)
        #pragma unroll
        for (int j = 0; j < 20; j++) acc[i][j] = 0.f;

    const int rowgrp = tid / 10;
    const int colgrp = tid - rowgrp * 10;
    const int c0 = colgrp * 20;

    for (int k0 = 0; k0 < DD; k0 += TK) {
        // commit prefetched tile to smem
        if (tid < 128) {
            int kb = apart * 4;
            As[kb + 0][arow] = pa.x; As[kb + 1][arow] = pa.y;
            As[kb + 2][arow] = pa.z; As[kb + 3][arow] = pa.w;
        }
        {
            float4* b4 = (float4*)&Bs[0][0];
            b4[tid] = pb0;
            b4[tid + 160] = pb1;
            if (tid < 80) b4[tid + 320] = pb2;
        }
        __syncthreads();

        // prefetch next tile (overlaps with FFMA burst below)
        int kn = k0 + TK;
        if (kn < DD) {
            pa = make_float4(0.f, 0.f, 0.f, 0.f);
            if (tid < 128 && arow < valid)
                pa = *(const float4*)(Ab + (size_t)(m0 + arow) * DD + kn + apart * 4);
            const float4* w4 = (const float4*)(Wr + (size_t)kn * DD);
            pb0 = w4[tid];
            pb1 = w4[tid + 160];
            if (tid < 80) pb2 = w4[tid + 320];
        }

        // compute: all indices compile-time
        #pragma unroll
        for (int kk = 0; kk < TK; kk++) {
            float4 a = *(const float4*)&As[kk][rowgrp * 4];
            float av[4] = {a.x, a.y, a.z, a.w};
            #pragma unroll
            for (int j = 0; j < 5; j++) {
                float4 b = *(const float4*)&Bs[kk][c0 + j * 4];
                float bv[4] = {b.x, b.y, b.z, b.w};
                #pragma unroll
                for (int i = 0; i < 4; i++) {
                    acc[i][j*4+0] = fmaf(av[i], bv[0], acc[i][j*4+0]);
                    acc[i][j*4+1] = fmaf(av[i], bv[1], acc[i][j*4+1]);
                    acc[i][j*4+2] = fmaf(av[i], bv[2], acc[i][j*4+2]);
                    acc[i][j*4+3] = fmaf(av[i], bv[3], acc[i][j*4+3]);
                }
            }
        }
        __syncthreads();
    }

    // epilogue
    #pragma unroll
    for (int i = 0; i < 4; i++) {
        int row = rowgrp * 4 + i;
        if (row >= valid) continue;
        int n = REL ? g_list[r * NN + m0 + row] : (m0 + row);
        float* op = out + (size_t)n * DD + c0;
        if (REL) {
            #pragma unroll
            for (int j = 0; j < 5; j++) {
                float4 v = make_float4(acc[i][j*4+0], acc[i][j*4+1],
                                       acc[i][j*4+2], acc[i][j*4+3]);
                red4(op + j * 4, v);
            }
        } else {
            #pragma unroll
            for (int j = 0; j < 5; j++) {
                float4 v;
                v.x = acc[i][j*4+0] + bias[c0 + j*4 + 0];
                v.y = acc[i][j*4+1] + bias[c0 + j*4 + 1];
                v.z = acc[i][j*4+2] + bias[c0 + j*4 + 2];
                v.w = acc[i][j*4+3] + bias[c0 + j*4 + 3];
                *(float4*)(op + j * 4) = v;
            }
        }
    }
}

// ---------------- launch -----------------------------------------------------

extern "C" void kernel_launch(void* const* d_in, const int* in_sizes, int n_in,
                              void* d_out, int out_size) {
    const int*   ei    = (const int*)d_in[0];
    const int*   et    = (const int*)d_in[1];
    const float* emb   = (const float*)d_in[2];
    const float* W1    = (const float*)d_in[3];
    const float* root1 = (const float*)d_in[4];
    const float* b1    = (const float*)d_in[5];
    const float* W2    = (const float*)d_in[6];
    const float* root2 = (const float*)d_in[7];
    const float* b2    = (const float*)d_in[8];
    float* out = (float*)d_out;

    const int* src = ei;
    const int* dst = ei + EE;

    float* hptr = nullptr;
    cudaGetSymbolAddress((void**)&hptr, g_h);

    const int mb = (NN + BM - 1) / BM;          // 782
    const int eb = (EE + 255) / 256;
    const int sb = (NSEG + 255) / 256;

    // ---- one-time CSR + compaction (graph is layer-invariant) ----
    k_init<<<1024, 256>>>();
    k_count<<<eb, 256>>>(dst, et);
    k_scan1<<<NBLK, 1024>>>();
    k_scan2<<<1, 1024>>>();
    k_scan3<<<NBLK, 1024>>>();
    k_fill<<<eb, 256>>>(src, dst, et);
    k_compact<<<sb, 256>>>();

    // ---- layer 1 ----
    k_mean<<<dim3((NN + 7) / 8, RR), 256>>>(emb);
    k_gemm<false><<<dim3(mb, 1), NT>>>(emb, root1, b1, hptr);
    k_gemm<true ><<<dim3(mb, RR), NT>>>(nullptr, W1, nullptr, hptr);
    k_relu<<<2048, 256>>>();

    // ---- layer 2 ----
    k_mean<<<dim3((NN + 7) / 8, RR), 256>>>(hptr);
    k_gemm<false><<<dim3(mb, 1), NT>>>(hptr, root2, b2, out);
    k_gemm<true ><<<dim3(mb, RR), NT>>>(nullptr, W2, nullptr, out);
}

// round 11
// speedup vs baseline: 33.7194x; 1.1427x over previous
#include <cuda_runtime.h>
#include <cuda_bf16.h>
#include <cstdint>

#define NN 50000
#define RR 16
#define DD 200
#define EE 400000
#define KPAD 256

#define NSEG (RR * NN)
#define NBLK ((NSEG + 1023) / 1024)

// ---------------- scratch (device globals) ----------------------------------
__device__ __align__(128) __nv_bfloat16 g_meanh[(size_t)RR * NN * KPAD];
__device__ __align__(128) __nv_bfloat16 g_meanl[(size_t)RR * NN * KPAD];
__device__ __align__(128) __nv_bfloat16 g_xh[(size_t)NN * KPAD];
__device__ __align__(128) __nv_bfloat16 g_xl[(size_t)NN * KPAD];
__device__ __align__(128) __nv_bfloat16 g_Bh[17 * DD * KPAD];  // [slot][n][k], slot16=root
__device__ __align__(128) __nv_bfloat16 g_Bl[17 * DD * KPAD];
__device__ int   g_cnt[NSEG];
__device__ int   g_cur[NSEG];
__device__ int   g_off[NSEG];
__device__ int   g_bsum[1024];
__device__ int   g_srcids[EE];
__device__ int   g_list[NSEG];
__device__ int   g_listcnt[RR];
__device__ __align__(128) float g_h[NN * DD];

// ---------------- PTX helpers (base-ISA only: no tcgen05/TMEM) --------------
__device__ __forceinline__ void red2(float* p, float x, float y) {
    asm volatile("red.global.add.v2.f32 [%0], {%1,%2};"
                 :: "l"(p), "f"(x), "f"(y) : "memory");
}
__device__ __forceinline__ uint32_t smem_u32(const void* p) {
    uint32_t a;
    asm("{ .reg .u64 t; cvta.to.shared.u64 t, %1; cvt.u32.u64 %0, t; }"
        : "=r"(a) : "l"(p));
    return a;
}
__device__ __forceinline__ void ldsm4(uint32_t& r0, uint32_t& r1,
                                      uint32_t& r2, uint32_t& r3, uint32_t a) {
    asm volatile("ldmatrix.sync.aligned.m8n8.x4.shared.b16 {%0,%1,%2,%3}, [%4];"
                 : "=r"(r0), "=r"(r1), "=r"(r2), "=r"(r3) : "r"(a));
}
__device__ __forceinline__ void mma16816(float* c,
                                         uint32_t a0, uint32_t a1, uint32_t a2, uint32_t a3,
                                         uint32_t b0, uint32_t b1) {
    asm volatile("mma.sync.aligned.m16n8k16.row.col.f32.bf16.bf16.f32 "
                 "{%0,%1,%2,%3}, {%4,%5,%6,%7}, {%8,%9}, {%0,%1,%2,%3};"
                 : "+f"(c[0]), "+f"(c[1]), "+f"(c[2]), "+f"(c[3])
                 : "r"(a0), "r"(a1), "r"(a2), "r"(a3), "r"(b0), "r"(b1));
}
#define SWZ128(o) ((o) ^ (((o) >> 3) & 0x70))

__device__ __forceinline__ void store_split4(__nv_bfloat16* hb, __nv_bfloat16* lb, float4 v) {
    __nv_bfloat16 h[4], l[4];
    float vv[4] = {v.x, v.y, v.z, v.w};
    #pragma unroll
    for (int i = 0; i < 4; i++) {
        h[i] = __float2bfloat16(vv[i]);
        l[i] = __float2bfloat16(vv[i] - __bfloat162float(h[i]));
    }
    *(uint2*)hb = *(const uint2*)h;
    *(uint2*)lb = *(const uint2*)l;
}

// ---------------- CSR preprocessing (one-time) -------------------------------
__global__ void k_init() {
    int stride = gridDim.x * blockDim.x;
    for (int i = blockIdx.x * blockDim.x + threadIdx.x; i < NSEG; i += stride) {
        g_cnt[i] = 0; g_cur[i] = 0;
    }
    if (blockIdx.x == 0 && threadIdx.x < RR) g_listcnt[threadIdx.x] = 0;
}
__global__ void k_count(const int* __restrict__ dst, const int* __restrict__ et) {
    int e = blockIdx.x * blockDim.x + threadIdx.x;
    if (e < EE) atomicAdd(&g_cnt[et[e] * NN + dst[e]], 1);
}
__global__ void k_scan1() {
    __shared__ int sh[1024];
    int i = blockIdx.x * 1024 + threadIdx.x;
    int v = (i < NSEG) ? g_cnt[i] : 0;
    sh[threadIdx.x] = v; __syncthreads();
    #pragma unroll
    for (int d = 1; d < 1024; d <<= 1) {
        int t = (threadIdx.x >= d) ? sh[threadIdx.x - d] : 0;
        __syncthreads(); sh[threadIdx.x] += t; __syncthreads();
    }
    if (i < NSEG) g_off[i] = sh[threadIdx.x] - v;
    if (threadIdx.x == 1023) g_bsum[blockIdx.x] = sh[1023];
}
__global__ void k_scan2() {
    __shared__ int sh[1024];
    int v = (threadIdx.x < NBLK) ? g_bsum[threadIdx.x] : 0;
    sh[threadIdx.x] = v; __syncthreads();
    #pragma unroll
    for (int d = 1; d < 1024; d <<= 1) {
        int t = (threadIdx.x >= d) ? sh[threadIdx.x - d] : 0;
        __syncthreads(); sh[threadIdx.x] += t; __syncthreads();
    }
    g_bsum[threadIdx.x] = sh[threadIdx.x] - v;
}
__global__ void k_scan3() {
    int i = blockIdx.x * 1024 + threadIdx.x;
    if (i < NSEG) g_off[i] += g_bsum[blockIdx.x];
}
__global__ void k_fill(const int* __restrict__ src, const int* __restrict__ dst,
                       const int* __restrict__ et) {
    int e = blockIdx.x * blockDim.x + threadIdx.x;
    if (e >= EE) return;
    int seg = et[e] * NN + dst[e];
    g_srcids[g_off[seg] + atomicAdd(&g_cur[seg], 1)] = src[e];
}
__global__ void k_compact() {
    int i = blockIdx.x * blockDim.x + threadIdx.x;
    if (i >= NSEG) return;
    if (g_cnt[i] > 0) {
        int r = i / NN, n = i - r * NN;
        g_list[r * NN + atomicAdd(&g_listcnt[r], 1)] = n;
    }
}

// ---------------- per-layer preprocessing ------------------------------------
// one warp per active (r,pos): gather-mean, split to bf16 halves (K padded 256)
__global__ void k_mean(const float* __restrict__ x) {
    int wid = threadIdx.x >> 5, lane = threadIdx.x & 31;
    int p = blockIdx.x * (blockDim.x >> 5) + wid;
    int r = blockIdx.y;
    if (p >= g_listcnt[r]) return;
    int seg = r * NN + g_list[r * NN + p];
    int o0 = g_off[seg], deg = g_cnt[seg];
    float inv = 1.0f / (float)deg;

    float4 a0 = make_float4(0.f, 0.f, 0.f, 0.f);
    float4 a1 = a0;
    for (int e = 0; e < deg; e++) {
        const float4* xr = (const float4*)(x + (size_t)g_srcids[o0 + e] * DD);
        float4 v = xr[lane];
        a0.x += v.x; a0.y += v.y; a0.z += v.z; a0.w += v.w;
        if (lane < 18) {
            float4 w = xr[lane + 32];
            a1.x += w.x; a1.y += w.y; a1.z += w.z; a1.w += w.w;
        }
    }
    size_t base = ((size_t)r * NN + p) * KPAD;
    a0.x *= inv; a0.y *= inv; a0.z *= inv; a0.w *= inv;
    store_split4(g_meanh + base + lane * 4, g_meanl + base + lane * 4, a0);
    if (lane < 18) {
        a1.x *= inv; a1.y *= inv; a1.z *= inv; a1.w *= inv;
    } else {
        a1 = make_float4(0.f, 0.f, 0.f, 0.f);   // zero-pad cols 200..255
    }
    store_split4(g_meanh + base + 128 + lane * 4, g_meanl + base + 128 + lane * 4, a1);
}

// split node features x [NN,200] fp32 -> g_xh/g_xl [NN,256] bf16 (zero-padded)
__global__ void k_xsplit(const float* __restrict__ x) {
    int i = blockIdx.x * blockDim.x + threadIdx.x;
    if (i >= NN * 64) return;
    int row = i >> 6, c = i & 63;
    float4 v = make_float4(0.f, 0.f, 0.f, 0.f);
    if (c < 50) v = ((const float4*)(x + (size_t)row * DD))[c];
    size_t o = (size_t)row * KPAD + c * 4;
    store_split4(g_xh + o, g_xl + o, v);
}

// transpose+split weights: g_B?[slot][n][k] = W_slot[k][n]; slot 16 = root
__global__ void k_wsplit(const float* __restrict__ W, const float* __restrict__ root) {
    int i = blockIdx.x * blockDim.x + threadIdx.x;
    if (i >= 17 * DD * KPAD) return;
    int slot = i / (DD * KPAD);
    int rem = i - slot * DD * KPAD;
    int n = rem / KPAD, k = rem - n * KPAD;
    float v = 0.f;
    if (k < DD) v = (slot < 16) ? W[(size_t)slot * DD * DD + k * DD + n]
                                : root[k * DD + n];
    __nv_bfloat16 h = __float2bfloat16(v);
    g_Bh[i] = h;
    g_Bl[i] = __float2bfloat16(v - __bfloat162float(h));
}

__global__ void k_relu() {
    float4* h4 = (float4*)g_h;
    const int n4 = NN * DD / 4;
    for (int i = blockIdx.x * blockDim.x + threadIdx.x; i < n4;
         i += gridDim.x * blockDim.x) {
        float4 v = h4[i];
        v.x = fmaxf(v.x, 0.f); v.y = fmaxf(v.y, 0.f);
        v.z = fmaxf(v.z, 0.f); v.w = fmaxf(v.w, 0.f);
        h4[i] = v;
    }
}

// ---------------- HMMA GEMM (mma.sync bf16, 3-pass split) --------------------
// CTA: 512 thr (16 warps). M-tile 128, N 0..199 (+ padding tiles), K 208 eff.
// warp (mgrp = wid>>1, ngrp = wid&1): rows mgrp*16.., tile base ngrp*13,
// computes 14 n8-tiles (7 ldmatrix.x4 pairs), stores 13 (ngrp0) / 12 (ngrp1).
// REL=false: out[n] = D + bias (store). REL=true: out[g_list] += D (red.v2).
template <bool REL>
__global__ __launch_bounds__(512)
void k_mma(const float* __restrict__ bias, float* __restrict__ out) {
    const int r  = REL ? blockIdx.y : 0;
    const int m0 = blockIdx.x * 128;
    int valid = REL ? (g_listcnt[r] - m0) : (NN - m0);
    if (valid <= 0) return;
    if (valid > 128) valid = 128;
    const int slot = REL ? r : 16;

    const int tid  = threadIdx.x;
    const int wid  = tid >> 5, lane = tid & 31;
    const int mgrp = wid >> 1, ngrp = wid & 1;
    const int tb   = ngrp * 13;          // local tile base

    __shared__ __align__(1024) char sA[128 * 128];   // 128 rows x 64 bf16 SW128
    __shared__ __align__(1024) char sB[216 * 128];   // 216 rows x 64 bf16 SW128

    const uint32_t aAddr = smem_u32(sA);
    const uint32_t bAddr = smem_u32(sB);

    // ldmatrix lane-address components
    const int lg = lane >> 3, rs = lane & 7;
    const uint32_t a_row = mgrp * 16 + ((lg & 1) << 3) + rs;  // A: m-quadrant
    const uint32_t a_kb  = (uint32_t)(lg >> 1) << 4;          // A: k-half byte
    const uint32_t b_ro  = ((uint32_t)(lg >> 1) << 3) + rs;   // B: tile-in-pair row
    const uint32_t b_kb  = (uint32_t)(lg & 1) << 4;           // B: k-half byte

    const __nv_bfloat16* Ah = REL ? (g_meanh + (size_t)r * NN * KPAD) : g_xh;
    const __nv_bfloat16* Al = REL ? (g_meanl + (size_t)r * NN * KPAD) : g_xl;

    float acc[14][4];
    #pragma unroll
    for (int i = 0; i < 14; i++)
        #pragma unroll
        for (int j = 0; j < 4; j++) acc[i][j] = 0.f;

    #pragma unroll 1
    for (int pass = 0; pass < 3; pass++) {
        const __nv_bfloat16* Asrc = (pass == 1) ? Al : Ah;
        const __nv_bfloat16* Bsrc = ((pass == 2) ? g_Bl : g_Bh) + (size_t)slot * DD * KPAD;
        #pragma unroll 1
        for (int ch = 0; ch < 4; ch++) {
            // ---- fill smem tiles (chunk ch: cols ch*64.., width 64 or 16) ----
            if (ch < 3) {
                #pragma unroll
                for (int l = 0; l < 2; l++) {
                    int u = tid + l * 512;                  // 1024 A units
                    int row = u >> 3, g = u & 7;
                    float4 v = make_float4(0.f, 0.f, 0.f, 0.f);
                    if (row < valid)
                        v = *(const float4*)(Asrc + (size_t)(m0 + row) * KPAD + ch * 64 + g * 8);
                    *(float4*)(sA + SWZ128((uint32_t)(row * 128 + g * 16))) = v;
                }
                #pragma unroll 1
                for (int u = tid; u < 1600; u += 512) {     // 200 B rows x 8
                    int row = u >> 3, g = u & 7;
                    float4 v = *(const float4*)(Bsrc + (size_t)row * KPAD + ch * 64 + g * 8);
                    *(float4*)(sB + SWZ128((uint32_t)(row * 128 + g * 16))) = v;
                }
            } else {
                if (tid < 256) {                            // 128 A rows x 2
                    int row = tid >> 1, g = tid & 1;
                    float4 v = make_float4(0.f, 0.f, 0.f, 0.f);
                    if (row < valid)
                        v = *(const float4*)(Asrc + (size_t)(m0 + row) * KPAD + 192 + g * 8);
                    *(float4*)(sA + SWZ128((uint32_t)(row * 128 + g * 16))) = v;
                }
                if (tid < 400) {                            // 200 B rows x 2
                    int row = tid >> 1, g = tid & 1;
                    float4 v = *(const float4*)(Bsrc + (size_t)row * KPAD + 192 + g * 8);
                    *(float4*)(sB + SWZ128((uint32_t)(row * 128 + g * 16))) = v;
                }
            }
            __syncthreads();

            const int nk16 = (ch < 3) ? 4 : 1;
            #pragma unroll 1
            for (int k16 = 0; k16 < nk16; k16++) {
                const uint32_t kbase = (uint32_t)k16 * 32;
                uint32_t a0, a1, a2, a3;
                ldsm4(a0, a1, a2, a3,
                      aAddr + SWZ128(a_row * 128 + kbase + a_kb));
                #pragma unroll
                for (int p = 0; p < 7; p++) {
                    uint32_t b0, b1, b2, b3;
                    uint32_t nrow = (uint32_t)(tb + 2 * p) * 8 + b_ro;
                    ldsm4(b0, b1, b2, b3,
                          bAddr + SWZ128(nrow * 128 + kbase + b_kb));
                    mma16816(acc[2 * p],     a0, a1, a2, a3, b0, b1);
                    mma16816(acc[2 * p + 1], a0, a1, a2, a3, b2, b3);
                }
            }
            __syncthreads();
        }
    }

    // ---- epilogue ----
    const int rlo = lane >> 2;
    const int cq  = (lane & 3) * 2;
    const int ntl = ngrp ? 12 : 13;      // tiles stored: ngrp0 -> 0..12, ngrp1 -> 13..24
    #pragma unroll
    for (int h = 0; h < 2; h++) {
        int lrow = mgrp * 16 + rlo + h * 8;
        if (lrow < valid) {
            int n = REL ? g_list[r * NN + m0 + lrow] : (m0 + lrow);
            float* op = out + (size_t)n * DD;
            #pragma unroll
            for (int tl = 0; tl < 13; tl++) {
                if (tl < ntl) {
                    int col = (tb + tl) * 8 + cq;
                    if (REL) {
                        red2(op + col, acc[tl][h * 2], acc[tl][h * 2 + 1]);
                    } else {
                        float2 bv = *(const float2*)(bias + col);
                        float2 v;
                        v.x = acc[tl][h * 2]     + bv.x;
                        v.y = acc[tl][h * 2 + 1] + bv.y;
                        *(float2*)(op + col) = v;
                    }
                }
            }
        }
    }
}

// ---------------- launch -------------------------------------------------------
extern "C" void kernel_launch(void* const* d_in, const int* in_sizes, int n_in,
                              void* d_out, int out_size) {
    const int*   ei    = (const int*)d_in[0];
    const int*   et    = (const int*)d_in[1];
    const float* emb   = (const float*)d_in[2];
    const float* W1    = (const float*)d_in[3];
    const float* root1 = (const float*)d_in[4];
    const float* b1    = (const float*)d_in[5];
    const float* W2    = (const float*)d_in[6];
    const float* root2 = (const float*)d_in[7];
    const float* b2    = (const float*)d_in[8];
    float* out = (float*)d_out;

    const int* src = ei;
    const int* dst = ei + EE;

    float* hptr = nullptr;
    cudaGetSymbolAddress((void**)&hptr, g_h);

    const int mb = (NN + 127) / 128;            // 391
    const int eb = (EE + 255) / 256;
    const int sb = (NSEG + 255) / 256;
    const int xs = (NN * 64 + 255) / 256;
    const int ws = (17 * DD * KPAD + 255) / 256;

    // ---- one-time CSR + compaction ----
    k_init<<<1024, 256>>>();
    k_count<<<eb, 256>>>(dst, et);
    k_scan1<<<NBLK, 1024>>>();
    k_scan2<<<1, 1024>>>();
    k_scan3<<<NBLK, 1024>>>();
    k_fill<<<eb, 256>>>(src, dst, et);
    k_compact<<<sb, 256>>>();

    // ---- layer 1 ----
    k_wsplit<<<ws, 256>>>(W1, root1);
    k_xsplit<<<xs, 256>>>(emb);
    k_mean<<<dim3((NN + 7) / 8, RR), 256>>>(emb);
    k_mma<false><<<dim3(mb, 1), 512>>>(b1, hptr);
    k_mma<true ><<<dim3(mb, RR), 512>>>(nullptr, hptr);
    k_relu<<<2048, 256>>>();

    // ---- layer 2 ----
    k_wsplit<<<ws, 256>>>(W2, root2);
    k_xsplit<<<xs, 256>>>(hptr);
    k_mean<<<dim3((NN + 7) / 8, RR), 256>>>(hptr);
    k_mma<false><<<dim3(mb, 1), 512>>>(b2, out);
    k_mma<true ><<<dim3(mb, RR), 512>>>(nullptr, out);
}

// round 13
// speedup vs baseline: 49.5924x; 1.4707x over previous
#include <cuda_runtime.h>
#include <cuda_bf16.h>
#include <cstdint>

#define NN 50000
#define RR 16
#define DD 200
#define EE 400000
#define KPAD 256

#define NSEG (RR * NN)
#define NBLK ((NSEG + 1023) / 1024)

#define ABYTES 16384            // 128 rows x 128B
#define BBYTES 27648            // 216 rows x 128B (8 pad rows for ldsm overreach)
#define SMEM_TOTAL (2 * ABYTES + 2 * BBYTES)   // 88064

// ---------------- scratch (device globals) ----------------------------------
__device__ __align__(128) __nv_bfloat16 g_meanh[(size_t)RR * NN * KPAD];
__device__ __align__(128) __nv_bfloat16 g_meanl[(size_t)RR * NN * KPAD];
__device__ __align__(128) __nv_bfloat16 g_xh[(size_t)NN * KPAD];
__device__ __align__(128) __nv_bfloat16 g_xl[(size_t)NN * KPAD];
__device__ __align__(128) __nv_bfloat16 g_Bh[17 * DD * KPAD];  // [slot][n][k], slot16=root
__device__ __align__(128) __nv_bfloat16 g_Bl[17 * DD * KPAD];
__device__ int   g_cnt[NSEG];
__device__ int   g_cur[NSEG];
__device__ int   g_off[NSEG];
__device__ int   g_bsum[1024];
__device__ int   g_srcids[EE];
__device__ int   g_list[NSEG];
__device__ int   g_listcnt[RR];
__device__ __align__(128) float g_h[NN * DD];

// ---------------- PTX helpers (base ISA only) --------------------------------
__device__ __forceinline__ void red2(float* p, float x, float y) {
    asm volatile("red.global.add.v2.f32 [%0], {%1,%2};"
                 :: "l"(p), "f"(x), "f"(y) : "memory");
}
__device__ __forceinline__ uint32_t smem_u32(const void* p) {
    uint32_t a;
    asm("{ .reg .u64 t; cvta.to.shared.u64 t, %1; cvt.u32.u64 %0, t; }"
        : "=r"(a) : "l"(p));
    return a;
}
__device__ __forceinline__ void ldsm4(uint32_t& r0, uint32_t& r1,
                                      uint32_t& r2, uint32_t& r3, uint32_t a) {
    asm volatile("ldmatrix.sync.aligned.m8n8.x4.shared.b16 {%0,%1,%2,%3}, [%4];"
                 : "=r"(r0), "=r"(r1), "=r"(r2), "=r"(r3) : "r"(a));
}
__device__ __forceinline__ void mma16816(float* c,
                                         uint32_t a0, uint32_t a1, uint32_t a2, uint32_t a3,
                                         uint32_t b0, uint32_t b1) {
    asm volatile("mma.sync.aligned.m16n8k16.row.col.f32.bf16.bf16.f32 "
                 "{%0,%1,%2,%3}, {%4,%5,%6,%7}, {%8,%9}, {%0,%1,%2,%3};"
                 : "+f"(c[0]), "+f"(c[1]), "+f"(c[2]), "+f"(c[3])
                 : "r"(a0), "r"(a1), "r"(a2), "r"(a3), "r"(b0), "r"(b1));
}
__device__ __forceinline__ void cpa16(uint32_t dst, const void* src, uint32_t srcbytes) {
    asm volatile("cp.async.cg.shared.global [%0], [%1], 16, %2;"
                 :: "r"(dst), "l"(src), "r"(srcbytes) : "memory");
}
#define CPA_COMMIT() asm volatile("cp.async.commit_group;" ::: "memory")
#define CPA_WAIT(n)  asm volatile("cp.async.wait_group %0;" :: "n"(n) : "memory")
#define SWZ128(o) ((o) ^ (((o) >> 3) & 0x70))

__device__ __forceinline__ void store_split4(__nv_bfloat16* hb, __nv_bfloat16* lb, float4 v) {
    __nv_bfloat16 h[4], l[4];
    float vv[4] = {v.x, v.y, v.z, v.w};
    #pragma unroll
    for (int i = 0; i < 4; i++) {
        h[i] = __float2bfloat16(vv[i]);
        l[i] = __float2bfloat16(vv[i] - __bfloat162float(h[i]));
    }
    *(uint2*)hb = *(const uint2*)h;
    *(uint2*)lb = *(const uint2*)l;
}

// ---------------- CSR preprocessing (one-time) -------------------------------
__global__ void k_init() {
    int stride = gridDim.x * blockDim.x;
    for (int i = blockIdx.x * blockDim.x + threadIdx.x; i < NSEG; i += stride) {
        g_cnt[i] = 0; g_cur[i] = 0;
    }
    if (blockIdx.x == 0 && threadIdx.x < RR) g_listcnt[threadIdx.x] = 0;
}
__global__ void k_count(const int* __restrict__ dst, const int* __restrict__ et) {
    int e = blockIdx.x * blockDim.x + threadIdx.x;
    if (e < EE) atomicAdd(&g_cnt[et[e] * NN + dst[e]], 1);
}
__global__ void k_scan1() {
    __shared__ int sh[1024];
    int i = blockIdx.x * 1024 + threadIdx.x;
    int v = (i < NSEG) ? g_cnt[i] : 0;
    sh[threadIdx.x] = v; __syncthreads();
    #pragma unroll
    for (int d = 1; d < 1024; d <<= 1) {
        int t = (threadIdx.x >= d) ? sh[threadIdx.x - d] : 0;
        __syncthreads(); sh[threadIdx.x] += t; __syncthreads();
    }
    if (i < NSEG) g_off[i] = sh[threadIdx.x] - v;
    if (threadIdx.x == 1023) g_bsum[blockIdx.x] = sh[1023];
}
__global__ void k_scan2() {
    __shared__ int sh[1024];
    int v = (threadIdx.x < NBLK) ? g_bsum[threadIdx.x] : 0;
    sh[threadIdx.x] = v; __syncthreads();
    #pragma unroll
    for (int d = 1; d < 1024; d <<= 1) {
        int t = (threadIdx.x >= d) ? sh[threadIdx.x - d] : 0;
        __syncthreads(); sh[threadIdx.x] += t; __syncthreads();
    }
    g_bsum[threadIdx.x] = sh[threadIdx.x] - v;
}
__global__ void k_scan3() {
    int i = blockIdx.x * 1024 + threadIdx.x;
    if (i < NSEG) g_off[i] += g_bsum[blockIdx.x];
}
__global__ void k_fill(const int* __restrict__ src, const int* __restrict__ dst,
                       const int* __restrict__ et) {
    int e = blockIdx.x * blockDim.x + threadIdx.x;
    if (e >= EE) return;
    int seg = et[e] * NN + dst[e];
    g_srcids[g_off[seg] + atomicAdd(&g_cur[seg], 1)] = src[e];
}
__global__ void k_compact() {
    int i = blockIdx.x * blockDim.x + threadIdx.x;
    if (i >= NSEG) return;
    if (g_cnt[i] > 0) {
        int r = i / NN, n = i - r * NN;
        g_list[r * NN + atomicAdd(&g_listcnt[r], 1)] = n;
    }
}

// ---------------- per-layer preprocessing ------------------------------------
// one warp per active (r,pos): gather-mean, split to bf16 halves (cols 0..207)
__global__ void k_mean(const float* __restrict__ x) {
    int wid = threadIdx.x >> 5, lane = threadIdx.x & 31;
    int p = blockIdx.x * (blockDim.x >> 5) + wid;
    int r = blockIdx.y;
    if (p >= g_listcnt[r]) return;
    int seg = r * NN + g_list[r * NN + p];
    int o0 = g_off[seg], deg = g_cnt[seg];
    float inv = 1.0f / (float)deg;

    float4 a0 = make_float4(0.f, 0.f, 0.f, 0.f);
    float4 a1 = a0;
    for (int e = 0; e < deg; e++) {
        const float4* xr = (const float4*)(x + (size_t)g_srcids[o0 + e] * DD);
        float4 v = xr[lane];
        a0.x += v.x; a0.y += v.y; a0.z += v.z; a0.w += v.w;
        if (lane < 18) {
            float4 w = xr[lane + 32];
            a1.x += w.x; a1.y += w.y; a1.z += w.z; a1.w += w.w;
        }
    }
    size_t base = ((size_t)r * NN + p) * KPAD;
    a0.x *= inv; a0.y *= inv; a0.z *= inv; a0.w *= inv;
    store_split4(g_meanh + base + lane * 4, g_meanl + base + lane * 4, a0);
    if (lane < 20) {                    // cols 128..207 (lanes 18,19 -> zero pad)
        if (lane < 18) {
            a1.x *= inv; a1.y *= inv; a1.z *= inv; a1.w *= inv;
        } else {
            a1 = make_float4(0.f, 0.f, 0.f, 0.f);
        }
        store_split4(g_meanh + base + 128 + lane * 4, g_meanl + base + 128 + lane * 4, a1);
    }
}

// split node features x [NN,200] fp32 -> g_xh/g_xl bf16 (cols 0..207)
__global__ void k_xsplit(const float* __restrict__ x) {
    int i = blockIdx.x * blockDim.x + threadIdx.x;
    if (i >= NN * 64) return;
    int row = i >> 6, c = i & 63;
    if (c >= 52) return;                 // only cols 0..207
    float4 v = make_float4(0.f, 0.f, 0.f, 0.f);
    if (c < 50) v = ((const float4*)(x + (size_t)row * DD))[c];
    size_t o = (size_t)row * KPAD + c * 4;
    store_split4(g_xh + o, g_xl + o, v);
}

// transpose+split weights: g_B?[slot][n][k] = W_slot[k][n]; slot 16 = root
__global__ void k_wsplit(const float* __restrict__ W, const float* __restrict__ root) {
    int i = blockIdx.x * blockDim.x + threadIdx.x;
    if (i >= 17 * DD * KPAD) return;
    int slot = i / (DD * KPAD);
    int rem = i - slot * DD * KPAD;
    int n = rem / KPAD, k = rem - n * KPAD;
    if (k >= 208) return;                // cols 208..255 never read
    float v = 0.f;
    if (k < DD) v = (slot < 16) ? W[(size_t)slot * DD * DD + k * DD + n]
                                : root[k * DD + n];
    __nv_bfloat16 h = __float2bfloat16(v);
    g_Bh[i] = h;
    g_Bl[i] = __float2bfloat16(v - __bfloat162float(h));
}

__global__ void k_relu() {
    float4* h4 = (float4*)g_h;
    const int n4 = NN * DD / 4;
    for (int i = blockIdx.x * blockDim.x + threadIdx.x; i < n4;
         i += gridDim.x * blockDim.x) {
        float4 v = h4[i];
        v.x = fmaxf(v.x, 0.f); v.y = fmaxf(v.y, 0.f);
        v.z = fmaxf(v.z, 0.f); v.w = fmaxf(v.w, 0.f);
        h4[i] = v;
    }
}

// ---------------- HMMA GEMM: fused 12-chunk stream, cp.async double buffer ---
// chunk c: pass = c>>2 (Ah*Bh, Al*Bh, Ah*Bl), ch = c&3 (K cols ch*64, w=64/16)
// CTA 512 thr; warp (mgrp,ngrp): rows mgrp*16.., tiles tb=ngrp*13 (14 computed,
// 13/12 stored). REL=false: out = D+bias. REL=true: out[g_list] += D (red.v2).
template <bool REL>
__global__ __launch_bounds__(512)
void k_mma(const float* __restrict__ bias, float* __restrict__ out) {
    extern __shared__ char dsm[];
    const int r  = REL ? blockIdx.y : 0;
    const int m0 = blockIdx.x * 128;
    int valid = REL ? (g_listcnt[r] - m0) : (NN - m0);
    if (valid <= 0) return;
    if (valid > 128) valid = 128;
    const int slot = REL ? r : 16;

    const int tid  = threadIdx.x;
    const int wid  = tid >> 5, lane = tid & 31;
    const int mgrp = wid >> 1, ngrp = wid & 1;
    const int tb   = ngrp * 13;

    const uint32_t sbase = smem_u32(dsm);

    const __nv_bfloat16* Ah = REL ? (g_meanh + (size_t)r * NN * KPAD) : g_xh;
    const __nv_bfloat16* Al = REL ? (g_meanl + (size_t)r * NN * KPAD) : g_xl;
    const __nv_bfloat16* Bh = g_Bh + (size_t)slot * DD * KPAD;
    const __nv_bfloat16* Bl = g_Bl + (size_t)slot * DD * KPAD;

    // ldmatrix lane-address components
    const int lg = lane >> 3, rs = lane & 7;
    const uint32_t a_row = mgrp * 16 + ((lg & 1) << 3) + rs;
    const uint32_t a_kb  = (uint32_t)(lg >> 1) << 4;
    const uint32_t b_ro  = ((uint32_t)(lg >> 1) << 3) + rs;
    const uint32_t b_kb  = (uint32_t)(lg & 1) << 4;

    float acc[14][4];
    #pragma unroll
    for (int i = 0; i < 14; i++)
        #pragma unroll
        for (int j = 0; j < 4; j++) acc[i][j] = 0.f;

    // async fill of chunk c into buffer c&1
    auto fill = [&](int c) {
        const int pass = c >> 2, ch = c & 3;
        const __nv_bfloat16* As = (pass == 1) ? Al : Ah;
        const __nv_bfloat16* Bs = (pass == 2) ? Bl : Bh;
        const uint32_t aB = sbase + (uint32_t)(c & 1) * ABYTES;
        const uint32_t bB = sbase + 2 * ABYTES + (uint32_t)(c & 1) * BBYTES;
        const int cb = ch * 64;
        if (ch < 3) {
            #pragma unroll
            for (int l = 0; l < 2; l++) {              // A: 1024 x 16B
                int u = tid + l * 512;
                int row = u >> 3, g = u & 7;
                int rr = (row < valid) ? row : 0;       // clamp ptr, zfill via size
                cpa16(aB + SWZ128((uint32_t)(row * 128 + g * 16)),
                      As + (size_t)(m0 + rr) * KPAD + cb + g * 8,
                      (row < valid) ? 16u : 0u);
            }
            #pragma unroll
            for (int l = 0; l < 4; l++) {              // B: 1600 x 16B
                int u = tid + l * 512;
                if (u < 1600) {
                    int row = u >> 3, g = u & 7;
                    cpa16(bB + SWZ128((uint32_t)(row * 128 + g * 16)),
                          Bs + (size_t)row * KPAD + cb + g * 8, 16u);
                }
            }
        } else {
            if (tid < 256) {                           // A: 128 rows x 2
                int row = tid >> 1, g = tid & 1;
                int rr = (row < valid) ? row : 0;
                cpa16(aB + SWZ128((uint32_t)(row * 128 + g * 16)),
                      As + (size_t)(m0 + rr) * KPAD + 192 + g * 8,
                      (row < valid) ? 16u : 0u);
            }
            if (tid < 400) {                           // B: 200 rows x 2
                int row = tid >> 1, g = tid & 1;
                cpa16(bB + SWZ128((uint32_t)(row * 128 + g * 16)),
                      Bs + (size_t)row * KPAD + 192 + g * 8, 16u);
            }
        }
    };

    fill(0);
    CPA_COMMIT();

    #pragma unroll 1
    for (int c = 0; c < 12; c++) {
        if (c < 11) {
            fill(c + 1);
            CPA_COMMIT();
            CPA_WAIT(1);          // chunk c resident; chunk c+1 in flight
        } else {
            CPA_WAIT(0);
        }
        __syncthreads();

        const uint32_t aB = sbase + (uint32_t)(c & 1) * ABYTES;
        const uint32_t bB = sbase + 2 * ABYTES + (uint32_t)(c & 1) * BBYTES;
        const int nk16 = ((c & 3) < 3) ? 4 : 1;
        #pragma unroll 1
        for (int k16 = 0; k16 < nk16; k16++) {
            const uint32_t kbase = (uint32_t)k16 * 32;
            uint32_t a0, a1, a2, a3;
            ldsm4(a0, a1, a2, a3, aB + SWZ128(a_row * 128 + kbase + a_kb));
            #pragma unroll
            for (int p = 0; p < 7; p++) {
                uint32_t b0, b1, b2, b3;
                uint32_t nrow = (uint32_t)(tb + 2 * p) * 8 + b_ro;
                ldsm4(b0, b1, b2, b3, bB + SWZ128(nrow * 128 + kbase + b_kb));
                mma16816(acc[2 * p],     a0, a1, a2, a3, b0, b1);
                mma16816(acc[2 * p + 1], a0, a1, a2, a3, b2, b3);
            }
        }
        __syncthreads();          // buffer c&1 free for refill at iter c+1
    }

    // ---- epilogue ----
    const int rlo = lane >> 2;
    const int cq  = (lane & 3) * 2;
    const int ntl = ngrp ? 12 : 13;
    #pragma unroll
    for (int h = 0; h < 2; h++) {
        int lrow = mgrp * 16 + rlo + h * 8;
        if (lrow < valid) {
            int n = REL ? g_list[r * NN + m0 + lrow] : (m0 + lrow);
            float* op = out + (size_t)n * DD;
            #pragma unroll
            for (int tl = 0; tl < 13; tl++) {
                if (tl < ntl) {
                    int col = (tb + tl) * 8 + cq;
                    if (REL) {
                        red2(op + col, acc[tl][h * 2], acc[tl][h * 2 + 1]);
                    } else {
                        float2 bv = *(const float2*)(bias + col);
                        float2 v;
                        v.x = acc[tl][h * 2]     + bv.x;
                        v.y = acc[tl][h * 2 + 1] + bv.y;
                        *(float2*)(op + col) = v;
                    }
                }
            }
        }
    }
}

// ---------------- launch -------------------------------------------------------
extern "C" void kernel_launch(void* const* d_in, const int* in_sizes, int n_in,
                              void* d_out, int out_size) {
    const int*   ei    = (const int*)d_in[0];
    const int*   et    = (const int*)d_in[1];
    const float* emb   = (const float*)d_in[2];
    const float* W1    = (const float*)d_in[3];
    const float* root1 = (const float*)d_in[4];
    const float* b1    = (const float*)d_in[5];
    const float* W2    = (const float*)d_in[6];
    const float* root2 = (const float*)d_in[7];
    const float* b2    = (const float*)d_in[8];
    float* out = (float*)d_out;

    const int* src = ei;
    const int* dst = ei + EE;

    float* hptr = nullptr;
    cudaGetSymbolAddress((void**)&hptr, g_h);

    cudaFuncSetAttribute(k_mma<false>, cudaFuncAttributeMaxDynamicSharedMemorySize, SMEM_TOTAL);
    cudaFuncSetAttribute(k_mma<true >, cudaFuncAttributeMaxDynamicSharedMemorySize, SMEM_TOTAL);

    const int mb = (NN + 127) / 128;            // 391
    const int eb = (EE + 255) / 256;
    const int sb = (NSEG + 255) / 256;
    const int xs = (NN * 64 + 255) / 256;
    const int ws = (17 * DD * KPAD + 255) / 256;

    // ---- one-time CSR + compaction ----
    k_init<<<1024, 256>>>();
    k_count<<<eb, 256>>>(dst, et);
    k_scan1<<<NBLK, 1024>>>();
    k_scan2<<<1, 1024>>>();
    k_scan3<<<NBLK, 1024>>>();
    k_fill<<<eb, 256>>>(src, dst, et);
    k_compact<<<sb, 256>>>();

    // ---- layer 1 ----
    k_wsplit<<<ws, 256>>>(W1, root1);
    k_xsplit<<<xs, 256>>>(emb);
    k_mean<<<dim3((NN + 7) / 8, RR), 256>>>(emb);
    k_mma<false><<<dim3(mb, 1), 512, SMEM_TOTAL>>>(b1, hptr);
    k_mma<true ><<<dim3(mb, RR), 512, SMEM_TOTAL>>>(nullptr, hptr);
    k_relu<<<2048, 256>>>();

    // ---- layer 2 ----
    k_wsplit<<<ws, 256>>>(W2, root2);
    k_xsplit<<<xs, 256>>>(hptr);
    k_mean<<<dim3((NN + 7) / 8, RR), 256>>>(hptr);
    k_mma<false><<<dim3(mb, 1), 512, SMEM_TOTAL>>>(b2, out);
    k_mma<true ><<<dim3(mb, RR), 512, SMEM_TOTAL>>>(nullptr, out);
}

// round 14
// speedup vs baseline: 54.3743x; 1.0964x over previous
#include <cuda_runtime.h>
#include <cuda_bf16.h>
#include <cstdint>

#define NN 50000
#define RR 16
#define DD 200
#define EE 400000
#define KPAD 256

#define NSEG (RR * NN)
#define NBLK ((NSEG + 1023) / 1024)

#define ATILE 16384                     // one 128-row x 128B chunk tile
#define AH_OFF 0                        // 4 tiles: 64KB
#define AL_OFF (4 * ATILE)              // 4 tiles: 64KB
#define B_OFF  (8 * ATILE)              // double buffer
#define BBYTES 27648                    // 216 rows x 128B
#define SMEM_TOTAL (B_OFF + 2 * BBYTES) // 186368

// ---------------- scratch (device globals) ----------------------------------
__device__ __align__(128) __nv_bfloat16 g_Bh[17 * DD * KPAD];  // [slot][n][k], slot16=root
__device__ __align__(128) __nv_bfloat16 g_Bl[17 * DD * KPAD];
__device__ int   g_cnt[NSEG];
__device__ int   g_cur[NSEG];
__device__ int   g_off[NSEG];
__device__ int   g_bsum[1024];
__device__ int   g_srcids[EE];
__device__ int   g_list[NSEG];
__device__ int   g_listcnt[RR];
__device__ __align__(128) float g_h[NN * DD];

// ---------------- PTX helpers (base ISA only) --------------------------------
__device__ __forceinline__ void red2(float* p, float x, float y) {
    asm volatile("red.global.add.v2.f32 [%0], {%1,%2};"
                 :: "l"(p), "f"(x), "f"(y) : "memory");
}
__device__ __forceinline__ uint32_t smem_u32(const void* p) {
    uint32_t a;
    asm("{ .reg .u64 t; cvta.to.shared.u64 t, %1; cvt.u32.u64 %0, t; }"
        : "=r"(a) : "l"(p));
    return a;
}
__device__ __forceinline__ void ldsm4(uint32_t& r0, uint32_t& r1,
                                      uint32_t& r2, uint32_t& r3, uint32_t a) {
    asm volatile("ldmatrix.sync.aligned.m8n8.x4.shared.b16 {%0,%1,%2,%3}, [%4];"
                 : "=r"(r0), "=r"(r1), "=r"(r2), "=r"(r3) : "r"(a));
}
__device__ __forceinline__ void mma16816(float* c,
                                         uint32_t a0, uint32_t a1, uint32_t a2, uint32_t a3,
                                         uint32_t b0, uint32_t b1) {
    asm volatile("mma.sync.aligned.m16n8k16.row.col.f32.bf16.bf16.f32 "
                 "{%0,%1,%2,%3}, {%4,%5,%6,%7}, {%8,%9}, {%0,%1,%2,%3};"
                 : "+f"(c[0]), "+f"(c[1]), "+f"(c[2]), "+f"(c[3])
                 : "r"(a0), "r"(a1), "r"(a2), "r"(a3), "r"(b0), "r"(b1));
}
__device__ __forceinline__ void cpa16(uint32_t dst, const void* src) {
    asm volatile("cp.async.cg.shared.global [%0], [%1], 16;"
                 :: "r"(dst), "l"(src) : "memory");
}
#define CPA_COMMIT() asm volatile("cp.async.commit_group;" ::: "memory")
#define CPA_WAIT(n)  asm volatile("cp.async.wait_group %0;" :: "n"(n) : "memory")
#define SWZ128(o) ((o) ^ (((o) >> 3) & 0x70))

// ---------------- CSR preprocessing (one-time) -------------------------------
__global__ void k_init() {
    int stride = gridDim.x * blockDim.x;
    for (int i = blockIdx.x * blockDim.x + threadIdx.x; i < NSEG; i += stride) {
        g_cnt[i] = 0; g_cur[i] = 0;
    }
    if (blockIdx.x == 0 && threadIdx.x < RR) g_listcnt[threadIdx.x] = 0;
}
__global__ void k_count(const int* __restrict__ dst, const int* __restrict__ et) {
    int e = blockIdx.x * blockDim.x + threadIdx.x;
    if (e < EE) atomicAdd(&g_cnt[et[e] * NN + dst[e]], 1);
}
__global__ void k_scan1() {
    __shared__ int sh[1024];
    int i = blockIdx.x * 1024 + threadIdx.x;
    int v = (i < NSEG) ? g_cnt[i] : 0;
    sh[threadIdx.x] = v; __syncthreads();
    #pragma unroll
    for (int d = 1; d < 1024; d <<= 1) {
        int t = (threadIdx.x >= d) ? sh[threadIdx.x - d] : 0;
        __syncthreads(); sh[threadIdx.x] += t; __syncthreads();
    }
    if (i < NSEG) g_off[i] = sh[threadIdx.x] - v;
    if (threadIdx.x == 1023) g_bsum[blockIdx.x] = sh[1023];
}
__global__ void k_scan2() {
    __shared__ int sh[1024];
    int v = (threadIdx.x < NBLK) ? g_bsum[threadIdx.x] : 0;
    sh[threadIdx.x] = v; __syncthreads();
    #pragma unroll
    for (int d = 1; d < 1024; d <<= 1) {
        int t = (threadIdx.x >= d) ? sh[threadIdx.x - d] : 0;
        __syncthreads(); sh[threadIdx.x] += t; __syncthreads();
    }
    g_bsum[threadIdx.x] = sh[threadIdx.x] - v;
}
__global__ void k_scan3() {
    int i = blockIdx.x * 1024 + threadIdx.x;
    if (i < NSEG) g_off[i] += g_bsum[blockIdx.x];
}
__global__ void k_fill(const int* __restrict__ src, const int* __restrict__ dst,
                       const int* __restrict__ et) {
    int e = blockIdx.x * blockDim.x + threadIdx.x;
    if (e >= EE) return;
    int seg = et[e] * NN + dst[e];
    g_srcids[g_off[seg] + atomicAdd(&g_cur[seg], 1)] = src[e];
}
__global__ void k_compact() {
    int i = blockIdx.x * blockDim.x + threadIdx.x;
    if (i >= NSEG) return;
    if (g_cnt[i] > 0) {
        int r = i / NN, n = i - r * NN;
        g_list[r * NN + atomicAdd(&g_listcnt[r], 1)] = n;
    }
}

// transpose+split weights: g_B?[slot][n][k] = W_slot[k][n]; slot 16 = root
__global__ void k_wsplit(const float* __restrict__ W, const float* __restrict__ root) {
    int i = blockIdx.x * blockDim.x + threadIdx.x;
    if (i >= 17 * DD * KPAD) return;
    int slot = i / (DD * KPAD);
    int rem = i - slot * DD * KPAD;
    int n = rem / KPAD, k = rem - n * KPAD;
    if (k >= 208) return;                // cols 208..255 never read
    float v = 0.f;
    if (k < DD) v = (slot < 16) ? W[(size_t)slot * DD * DD + k * DD + n]
                                : root[k * DD + n];
    __nv_bfloat16 h = __float2bfloat16(v);
    g_Bh[i] = h;
    g_Bl[i] = __float2bfloat16(v - __bfloat162float(h));
}

// ---------------- fused gather-mean + HMMA GEMM ------------------------------
// A gathered in prologue (fp32 mean -> bf16 hi/lo split), resident in smem as
// 4 chunk tiles per half. B (pre-split, pre-transposed W) streams through a
// cp.async double buffer in 8 stages: s<4 -> Bh chunk s (Ah*Bh then Al*Bh),
// s>=4 -> Bl chunk s-4 (Ah*Bl). 39 k16 steps total (Markidis 3-term split).
// REL=false: identity rows, out = D + bias (store)
// REL=true : rows = active (r,seg) list, out[g_list] += D (red.global.v2)
// RELU: apply max(0,.) to xsrc reads (layer-2 fuses the ReLU here).
template <bool REL, bool RELU>
__global__ __launch_bounds__(512)
void k_mma(const float* __restrict__ xsrc, const float* __restrict__ bias,
           float* __restrict__ out) {
    extern __shared__ char dsm[];
    const int r  = REL ? blockIdx.y : 0;
    const int m0 = blockIdx.x * 128;
    int valid = REL ? (g_listcnt[r] - m0) : (NN - m0);
    if (valid <= 0) return;
    if (valid > 128) valid = 128;
    const int slot = REL ? r : 16;

    const int tid  = threadIdx.x;
    const int wid  = tid >> 5, lane = tid & 31;
    const int mgrp = wid >> 1, ngrp = wid & 1;
    const int tb   = ngrp * 13;

    const uint32_t sbase = smem_u32(dsm);
    const __nv_bfloat16* Bh = g_Bh + (size_t)slot * DD * KPAD;
    const __nv_bfloat16* Bl = g_Bl + (size_t)slot * DD * KPAD;

    // async fill of B stage s into buffer s&1
    auto fillB = [&](int s) {
        const int ch = s & 3;
        const __nv_bfloat16* Bs = (s < 4) ? Bh : Bl;
        const uint32_t bB = sbase + B_OFF + (uint32_t)(s & 1) * BBYTES;
        if (ch < 3) {
            #pragma unroll
            for (int l = 0; l < 4; l++) {
                int u = tid + l * 512;
                if (u < 1600) {
                    int row = u >> 3, g = u & 7;
                    cpa16(bB + SWZ128((uint32_t)(row * 128 + g * 16)),
                          Bs + (size_t)row * KPAD + ch * 64 + g * 8);
                }
            }
        } else {
            if (tid < 400) {
                int row = tid >> 1, g = tid & 1;
                cpa16(bB + SWZ128((uint32_t)(row * 128 + g * 16)),
                      Bs + (size_t)row * KPAD + 192 + g * 8);
            }
        }
    };

    fillB(0);
    CPA_COMMIT();

    // ---- gather A: warp w handles rows w, w+16, ..., w+112 ----
    // lane l < 25: cols l*8..l*8+7 (fp32 mean, optional relu, split to bf16)
    // lane 25: zero-pad cols 200..207; lanes 26..31 idle
    #pragma unroll 1
    for (int j = 0; j < 8; j++) {
        const int row = wid + j * 16;
        float s0[8];
        #pragma unroll
        for (int i = 0; i < 8; i++) s0[i] = 0.f;

        if (row < valid && lane < 25) {
            if (REL) {
                int n = g_list[r * NN + m0 + row];
                int seg = r * NN + n;
                int o0 = g_off[seg], deg = g_cnt[seg];
                for (int e = 0; e < deg; e++) {
                    const float4* xr = (const float4*)(xsrc +
                        (size_t)g_srcids[o0 + e] * DD + lane * 8);
                    float4 v0 = xr[0], v1 = xr[1];
                    if (RELU) {
                        v0.x = fmaxf(v0.x, 0.f); v0.y = fmaxf(v0.y, 0.f);
                        v0.z = fmaxf(v0.z, 0.f); v0.w = fmaxf(v0.w, 0.f);
                        v1.x = fmaxf(v1.x, 0.f); v1.y = fmaxf(v1.y, 0.f);
                        v1.z = fmaxf(v1.z, 0.f); v1.w = fmaxf(v1.w, 0.f);
                    }
                    s0[0] += v0.x; s0[1] += v0.y; s0[2] += v0.z; s0[3] += v0.w;
                    s0[4] += v1.x; s0[5] += v1.y; s0[6] += v1.z; s0[7] += v1.w;
                }
                float inv = 1.0f / (float)deg;
                #pragma unroll
                for (int i = 0; i < 8; i++) s0[i] *= inv;
            } else {
                const float4* xr = (const float4*)(xsrc +
                    (size_t)(m0 + row) * DD + lane * 8);
                float4 v0 = xr[0], v1 = xr[1];
                if (RELU) {
                    v0.x = fmaxf(v0.x, 0.f); v0.y = fmaxf(v0.y, 0.f);
                    v0.z = fmaxf(v0.z, 0.f); v0.w = fmaxf(v0.w, 0.f);
                    v1.x = fmaxf(v1.x, 0.f); v1.y = fmaxf(v1.y, 0.f);
                    v1.z = fmaxf(v1.z, 0.f); v1.w = fmaxf(v1.w, 0.f);
                }
                s0[0] = v0.x; s0[1] = v0.y; s0[2] = v0.z; s0[3] = v0.w;
                s0[4] = v1.x; s0[5] = v1.y; s0[6] = v1.z; s0[7] = v1.w;
            }
        }
        if (lane < 26) {
            __nv_bfloat16 hp[8], lp[8];
            #pragma unroll
            for (int i = 0; i < 8; i++) {
                hp[i] = __float2bfloat16(s0[i]);
                lp[i] = __float2bfloat16(s0[i] - __bfloat162float(hp[i]));
            }
            const int cb = lane * 8;
            const uint32_t sw = SWZ128((uint32_t)(row * 128 + (cb & 63) * 2));
            const uint32_t tbase = (uint32_t)(cb >> 6) * ATILE;
            *(uint4*)(dsm + AH_OFF + tbase + sw) = *(const uint4*)hp;
            *(uint4*)(dsm + AL_OFF + tbase + sw) = *(const uint4*)lp;
        }
    }

    // ldmatrix lane-address components
    const int lg = lane >> 3, rs = lane & 7;
    const uint32_t a_row = mgrp * 16 + ((lg & 1) << 3) + rs;
    const uint32_t a_kb  = (uint32_t)(lg >> 1) << 4;
    const uint32_t b_ro  = ((uint32_t)(lg >> 1) << 3) + rs;
    const uint32_t b_kb  = (uint32_t)(lg & 1) << 4;

    float acc[14][4];
    #pragma unroll
    for (int i = 0; i < 14; i++)
        #pragma unroll
        for (int j = 0; j < 4; j++) acc[i][j] = 0.f;

    __syncthreads();   // A resident & visible

    #pragma unroll 1
    for (int s = 0; s < 8; s++) {
        if (s < 7) {
            fillB(s + 1);
            CPA_COMMIT();
            CPA_WAIT(1);
        } else {
            CPA_WAIT(0);
        }
        __syncthreads();

        const uint32_t bB = sbase + B_OFF + (uint32_t)(s & 1) * BBYTES;
        const int ch = s & 3;
        const int nk16 = (ch < 3) ? 4 : 1;
        const int nsub = (s < 4) ? 2 : 1;
        #pragma unroll 1
        for (int sub = 0; sub < nsub; sub++) {
            const uint32_t aB = sbase + (sub ? AL_OFF : AH_OFF) + (uint32_t)ch * ATILE;
            #pragma unroll 1
            for (int k16 = 0; k16 < nk16; k16++) {
                const uint32_t kbase = (uint32_t)k16 * 32;
                uint32_t a0, a1, a2, a3;
                ldsm4(a0, a1, a2, a3, aB + SWZ128(a_row * 128 + kbase + a_kb));
                #pragma unroll
                for (int p = 0; p < 7; p++) {
                    uint32_t b0, b1, b2, b3;
                    uint32_t nrow = (uint32_t)(tb + 2 * p) * 8 + b_ro;
                    ldsm4(b0, b1, b2, b3, bB + SWZ128(nrow * 128 + kbase + b_kb));
                    mma16816(acc[2 * p],     a0, a1, a2, a3, b0, b1);
                    mma16816(acc[2 * p + 1], a0, a1, a2, a3, b2, b3);
                }
            }
        }
        __syncthreads();   // buffer s&1 free for refill
    }

    // ---- epilogue ----
    const int rlo = lane >> 2;
    const int cq  = (lane & 3) * 2;
    const int ntl = ngrp ? 12 : 13;
    #pragma unroll
    for (int h = 0; h < 2; h++) {
        int lrow = mgrp * 16 + rlo + h * 8;
        if (lrow < valid) {
            int n = REL ? g_list[r * NN + m0 + lrow] : (m0 + lrow);
            float* op = out + (size_t)n * DD;
            #pragma unroll
            for (int tl = 0; tl < 13; tl++) {
                if (tl < ntl) {
                    int col = (tb + tl) * 8 + cq;
                    if (REL) {
                        red2(op + col, acc[tl][h * 2], acc[tl][h * 2 + 1]);
                    } else {
                        float2 bv = *(const float2*)(bias + col);
                        float2 v;
                        v.x = acc[tl][h * 2]     + bv.x;
                        v.y = acc[tl][h * 2 + 1] + bv.y;
                        *(float2*)(op + col) = v;
                    }
                }
            }
        }
    }
}

// ---------------- launch -------------------------------------------------------
extern "C" void kernel_launch(void* const* d_in, const int* in_sizes, int n_in,
                              void* d_out, int out_size) {
    const int*   ei    = (const int*)d_in[0];
    const int*   et    = (const int*)d_in[1];
    const float* emb   = (const float*)d_in[2];
    const float* W1    = (const float*)d_in[3];
    const float* root1 = (const float*)d_in[4];
    const float* b1    = (const float*)d_in[5];
    const float* W2    = (const float*)d_in[6];
    const float* root2 = (const float*)d_in[7];
    const float* b2    = (const float*)d_in[8];
    float* out = (float*)d_out;

    const int* src = ei;
    const int* dst = ei + EE;

    float* hptr = nullptr;
    cudaGetSymbolAddress((void**)&hptr, g_h);

    cudaFuncSetAttribute(k_mma<false, false>, cudaFuncAttributeMaxDynamicSharedMemorySize, SMEM_TOTAL);
    cudaFuncSetAttribute(k_mma<true,  false>, cudaFuncAttributeMaxDynamicSharedMemorySize, SMEM_TOTAL);
    cudaFuncSetAttribute(k_mma<false, true >, cudaFuncAttributeMaxDynamicSharedMemorySize, SMEM_TOTAL);
    cudaFuncSetAttribute(k_mma<true,  true >, cudaFuncAttributeMaxDynamicSharedMemorySize, SMEM_TOTAL);

    const int mb = (NN + 127) / 128;            // 391
    const int eb = (EE + 255) / 256;
    const int sb = (NSEG + 255) / 256;
    const int ws = (17 * DD * KPAD + 255) / 256;

    // launch index:                                               (ncu: -s 5 -c 1)
    k_wsplit<<<ws, 256>>>(W1, root1);                                   // 0
    k_init<<<1024, 256>>>();                                            // 1
    k_count<<<eb, 256>>>(dst, et);                                      // 2
    k_scan1<<<NBLK, 1024>>>();                                          // 3
    k_scan2<<<1, 1024>>>();                                             // 4
    k_mma<false, false><<<dim3(mb, 1), 512, SMEM_TOTAL>>>(emb, b1, hptr); // 5 <- profiled
    k_scan3<<<NBLK, 1024>>>();                                          // 6
    k_fill<<<eb, 256>>>(src, dst, et);                                  // 7
    k_compact<<<sb, 256>>>();                                           // 8
    k_mma<true, false><<<dim3(mb, RR), 512, SMEM_TOTAL>>>(emb, nullptr, hptr); // 9
    k_wsplit<<<ws, 256>>>(W2, root2);                                   // 10
    k_mma<false, true><<<dim3(mb, 1), 512, SMEM_TOTAL>>>(hptr, b2, out);       // 11
    k_mma<true, true ><<<dim3(mb, RR), 512, SMEM_TOTAL>>>(hptr, nullptr, out); // 12
}